// round 6
// baseline (speedup 1.0000x reference)
#include <cuda_runtime.h>
#include <math.h>

#define NMAX 100000
#define EMAX 3200000
#define FIN  512
#define HID  256
#define NC   40

// ---------------- device scratch (static: no allocation) ----------------
__device__ int   g_is64;                  // edge_index dtype flag (1 = int64)
__device__ int   g_deg[NMAX];
__device__ float g_dinv[NMAX];
__device__ int   g_off[NMAX + 1];
__device__ int   g_cur[NMAX];
__device__ int   g_bsum[128];
__device__ int   g_bbase[128];
__device__ int   g_esrc[EMAX];
__device__ __align__(16) float g_y1[(size_t)NMAX * HID];   // dinv-scaled x@W1
__device__ __align__(16) float g_h [(size_t)NMAX * HID];   // layer-1 output (relu)
__device__ __align__(16) float g_y2[(size_t)NMAX * NC];    // dinv-scaled h@W2

// ---------------- edge index access (dtype-robust) ----------------
__device__ __forceinline__ int edge_at(const void* ei, int i) {
    if (g_is64) return (int)((const long long*)ei)[i];
    return ((const int*)ei)[i];
}

// Detect whether edge_index is int64 or int32. For int64 data with values in
// [0, n), every high word is 0 and every low word is a valid id. For int32
// random data in [0, n) the probability of 64 consecutive zero "high words"
// is ~0. Single thread, deterministic, graph-capturable.
__global__ void k_detect(const void* ei, int n) {
    if (blockIdx.x == 0 && threadIdx.x == 0) {
        const int* w = (const int*)ei;
        int is64 = 1;
        for (int i = 0; i < 64; i++) {
            int lo = w[2 * i], hi = w[2 * i + 1];
            if (hi != 0 || lo < 0 || lo >= n) { is64 = 0; break; }
        }
        g_is64 = is64;
    }
}

// ---------------- small utility kernels ----------------
__global__ void k_zero_deg(int n) {
    int i = blockIdx.x * blockDim.x + threadIdx.x;
    if (i < n) g_deg[i] = 0;
}

__global__ void k_hist(const void* __restrict__ ei, int E) {
    int e = blockIdx.x * blockDim.x + threadIdx.x;
    if (e < E) atomicAdd(&g_deg[edge_at(ei, E + e)], 1);
}

__global__ void k_dinv(int n) {
    int i = blockIdx.x * blockDim.x + threadIdx.x;
    if (i < n) g_dinv[i] = rsqrtf((float)(g_deg[i] + 1));   // +1 self loop
}

// ---------------- exclusive scan of g_deg -> g_off (3 kernels) ----------------
__global__ void k_scan1(int n) {
    __shared__ int sdata[256];
    int b = blockIdx.x, t = threadIdx.x;
    int base = b * 1024 + t * 4;
    int v0 = (base + 0 < n) ? g_deg[base + 0] : 0;
    int v1 = (base + 1 < n) ? g_deg[base + 1] : 0;
    int v2 = (base + 2 < n) ? g_deg[base + 2] : 0;
    int v3 = (base + 3 < n) ? g_deg[base + 3] : 0;
    int tsum = v0 + v1 + v2 + v3;
    sdata[t] = tsum;
    __syncthreads();
    for (int off = 1; off < 256; off <<= 1) {
        int x = 0;
        if (t >= off) x = sdata[t - off];
        __syncthreads();
        sdata[t] += x;
        __syncthreads();
    }
    int run = sdata[t] - tsum;   // exclusive prefix of this thread
    if (base + 0 < n) { g_off[base + 0] = run; run += v0; }
    if (base + 1 < n) { g_off[base + 1] = run; run += v1; }
    if (base + 2 < n) { g_off[base + 2] = run; run += v2; }
    if (base + 3 < n) { g_off[base + 3] = run; }
    if (t == 255) g_bsum[b] = sdata[255];
}

__global__ void k_scan2(int nb) {
    __shared__ int s[128];
    int t = threadIdx.x;
    int v = (t < nb) ? g_bsum[t] : 0;
    s[t] = v;
    __syncthreads();
    for (int off = 1; off < 128; off <<= 1) {
        int x = 0;
        if (t >= off) x = s[t - off];
        __syncthreads();
        s[t] += x;
        __syncthreads();
    }
    g_bbase[t] = s[t] - v;   // exclusive
}

__global__ void k_scan3(int n, int E) {
    int i = blockIdx.x * blockDim.x + threadIdx.x;
    if (i < n) {
        int o = g_off[i] + g_bbase[i >> 10];
        g_off[i] = o;
        g_cur[i] = o;
    }
    if (i == 0) g_off[n] = E;
}

__global__ void k_fill(const void* __restrict__ ei, int E) {
    int e = blockIdx.x * blockDim.x + threadIdx.x;
    if (e < E) {
        int r = edge_at(ei, e);          // source
        int c = edge_at(ei, E + e);      // target
        int pos = atomicAdd(&g_cur[c], 1);
        g_esrc[pos] = r;
    }
}

// ---------------- GEMM1: y1 = dinv .* (x @ W1)   [M,512]x[512,256] ----------------
// 128x128 block tile, 8x8 thread tile, 256 threads, BK=8, global prefetch.
__global__ __launch_bounds__(256) void k_sgemm1(const float* __restrict__ A,
                                                const float* __restrict__ B,
                                                int M) {
    __shared__ __align__(16) float As[8][128];
    __shared__ __align__(16) float Bs[8][128];
    int tid  = threadIdx.x;
    int row0 = blockIdx.x * 128;
    int col0 = blockIdx.y * 128;

    int a_r = tid >> 1;            // 0..127
    int a_k = (tid & 1) * 4;       // 0 or 4
    int b_k = tid >> 5;            // 0..7
    int b_n = (tid & 31) * 4;      // 0..124
    int tx  = tid & 15;            // col dir
    int ty  = tid >> 4;            // row dir

    float acc[8][8];
#pragma unroll
    for (int i = 0; i < 8; i++)
#pragma unroll
        for (int j = 0; j < 8; j++) acc[i][j] = 0.f;

    int arow = row0 + a_r;
    bool aval = arow < M;
    const float* Aptr = A + (size_t)arow * FIN + a_k;

    float4 av = aval ? *(const float4*)Aptr : make_float4(0.f, 0.f, 0.f, 0.f);
    float4 bv = *(const float4*)(B + (size_t)b_k * HID + col0 + b_n);

    for (int k0 = 0; k0 < FIN; k0 += 8) {
        As[a_k + 0][a_r] = av.x;
        As[a_k + 1][a_r] = av.y;
        As[a_k + 2][a_r] = av.z;
        As[a_k + 3][a_r] = av.w;
        *(float4*)&Bs[b_k][b_n] = bv;
        __syncthreads();

        if (k0 + 8 < FIN) {
            av = aval ? *(const float4*)(Aptr + k0 + 8)
                      : make_float4(0.f, 0.f, 0.f, 0.f);
            bv = *(const float4*)(B + (size_t)(k0 + 8 + b_k) * HID + col0 + b_n);
        }

#pragma unroll
        for (int kk = 0; kk < 8; kk++) {
            float4 a0 = *(const float4*)&As[kk][ty * 8];
            float4 a1 = *(const float4*)&As[kk][ty * 8 + 4];
            float4 c0 = *(const float4*)&Bs[kk][tx * 8];
            float4 c1 = *(const float4*)&Bs[kk][tx * 8 + 4];
            float a[8] = {a0.x, a0.y, a0.z, a0.w, a1.x, a1.y, a1.z, a1.w};
            float b[8] = {c0.x, c0.y, c0.z, c0.w, c1.x, c1.y, c1.z, c1.w};
#pragma unroll
            for (int i = 0; i < 8; i++)
#pragma unroll
                for (int j = 0; j < 8; j++) acc[i][j] += a[i] * b[j];
        }
        __syncthreads();
    }

#pragma unroll
    for (int i = 0; i < 8; i++) {
        int r = row0 + ty * 8 + i;
        if (r < M) {
            float d = g_dinv[r];
            float4 o0 = make_float4(d * acc[i][0], d * acc[i][1],
                                    d * acc[i][2], d * acc[i][3]);
            float4 o1 = make_float4(d * acc[i][4], d * acc[i][5],
                                    d * acc[i][6], d * acc[i][7]);
            float* yp = &g_y1[(size_t)r * HID + col0 + tx * 8];
            *(float4*)(yp)     = o0;
            *(float4*)(yp + 4) = o1;
        }
    }
}

// ---------------- Aggregation 1: h = relu(dinv*(sum y1[src] + y1[c]) + b1) ----------------
// one warp per node, 2 float4 per lane (256 features)
__global__ void k_agg1(const float* __restrict__ b1, int M) {
    int gid  = blockIdx.x * blockDim.x + threadIdx.x;
    int c    = gid >> 5;
    int lane = gid & 31;
    if (c >= M) return;

    const float4* Y = (const float4*)g_y1;
    float4 a0 = make_float4(0.f, 0.f, 0.f, 0.f);
    float4 a1 = make_float4(0.f, 0.f, 0.f, 0.f);

    int s0 = g_off[c], s1 = g_off[c + 1];
    for (int i = s0; i < s1; i++) {
        int s = g_esrc[i];
        const float4* rp = Y + (size_t)s * 64;
        float4 v0 = __ldg(rp + lane);
        float4 v1 = __ldg(rp + lane + 32);
        a0.x += v0.x; a0.y += v0.y; a0.z += v0.z; a0.w += v0.w;
        a1.x += v1.x; a1.y += v1.y; a1.z += v1.z; a1.w += v1.w;
    }
    // self loop
    {
        const float4* rp = Y + (size_t)c * 64;
        float4 v0 = __ldg(rp + lane);
        float4 v1 = __ldg(rp + lane + 32);
        a0.x += v0.x; a0.y += v0.y; a0.z += v0.z; a0.w += v0.w;
        a1.x += v1.x; a1.y += v1.y; a1.z += v1.z; a1.w += v1.w;
    }
    float d = g_dinv[c];
    float4 bb0 = make_float4(__ldg(b1 + lane * 4 + 0), __ldg(b1 + lane * 4 + 1),
                             __ldg(b1 + lane * 4 + 2), __ldg(b1 + lane * 4 + 3));
    float4 bb1 = make_float4(__ldg(b1 + 128 + lane * 4 + 0), __ldg(b1 + 128 + lane * 4 + 1),
                             __ldg(b1 + 128 + lane * 4 + 2), __ldg(b1 + 128 + lane * 4 + 3));
    float4 o0, o1;
    o0.x = fmaxf(d * a0.x + bb0.x, 0.f);
    o0.y = fmaxf(d * a0.y + bb0.y, 0.f);
    o0.z = fmaxf(d * a0.z + bb0.z, 0.f);
    o0.w = fmaxf(d * a0.w + bb0.w, 0.f);
    o1.x = fmaxf(d * a1.x + bb1.x, 0.f);
    o1.y = fmaxf(d * a1.y + bb1.y, 0.f);
    o1.z = fmaxf(d * a1.z + bb1.z, 0.f);
    o1.w = fmaxf(d * a1.w + bb1.w, 0.f);
    float4* H = (float4*)g_h;
    H[(size_t)c * 64 + lane]      = o0;
    H[(size_t)c * 64 + lane + 32] = o1;
}

// ---------------- GEMM2: y2 = dinv .* (h @ W2)   [M,256]x[256,40] ----------------
// 256 rows per block, 256 threads, BK=16; thread computes 4 rows x 10 cols.
__global__ __launch_bounds__(256) void k_sgemm2(const float* __restrict__ W2, int M) {
    __shared__ __align__(16) float hs[16][260];      // [k][row], padded
    __shared__ __align__(16) float ws[16 * NC];      // [k][40]
    int tid = threadIdx.x;
    int R0  = blockIdx.x * 256;
    int kv  = tid & 3;                 // loader: k group
    int rld = tid >> 2;                // loader: row 0..63
    int cg  = tid & 3;                 // compute: col group (10 cols)
    int rq  = tid >> 2;                // compute: row quad  (4 rows)

    float acc[4][10];
#pragma unroll
    for (int i = 0; i < 4; i++)
#pragma unroll
        for (int j = 0; j < 10; j++) acc[i][j] = 0.f;

    for (int k0 = 0; k0 < HID; k0 += 16) {
#pragma unroll
        for (int p = 0; p < 4; p++) {
            int rr = rld + p * 64;
            int gr = R0 + rr;
            float4 v = (gr < M)
                ? *(const float4*)&g_h[(size_t)gr * HID + k0 + kv * 4]
                : make_float4(0.f, 0.f, 0.f, 0.f);
            hs[kv * 4 + 0][rr] = v.x;
            hs[kv * 4 + 1][rr] = v.y;
            hs[kv * 4 + 2][rr] = v.z;
            hs[kv * 4 + 3][rr] = v.w;
        }
        if (tid < 160) {
            const float* wp = W2 + (size_t)k0 * NC + tid * 4;
            ws[tid * 4 + 0] = wp[0];
            ws[tid * 4 + 1] = wp[1];
            ws[tid * 4 + 2] = wp[2];
            ws[tid * 4 + 3] = wp[3];
        }
        __syncthreads();

#pragma unroll
        for (int kk = 0; kk < 16; kk++) {
            float h0 = hs[kk][rq * 4 + 0];
            float h1 = hs[kk][rq * 4 + 1];
            float h2 = hs[kk][rq * 4 + 2];
            float h3 = hs[kk][rq * 4 + 3];
#pragma unroll
            for (int j = 0; j < 10; j++) {
                float w = ws[kk * NC + cg * 10 + j];
                acc[0][j] += h0 * w;
                acc[1][j] += h1 * w;
                acc[2][j] += h2 * w;
                acc[3][j] += h3 * w;
            }
        }
        __syncthreads();
    }

#pragma unroll
    for (int i = 0; i < 4; i++) {
        int r = R0 + rq * 4 + i;
        if (r < M) {
            float d = g_dinv[r];
            float* yp = &g_y2[(size_t)r * NC + cg * 10];
#pragma unroll
            for (int j = 0; j < 10; j++) yp[j] = d * acc[i][j];
        }
    }
}

// ---------------- Aggregation 2 + bias + log_softmax ----------------
// one warp per node; lane l owns col l, and col 32+l for l<8.
__global__ void k_agg2_softmax(const float* __restrict__ b2,
                               float* __restrict__ out, int M) {
    int gid  = blockIdx.x * blockDim.x + threadIdx.x;
    int c    = gid >> 5;
    int l    = gid & 31;
    if (c >= M) return;

    float a0 = 0.f, a1 = 0.f;
    int s0 = g_off[c], s1 = g_off[c + 1];
    for (int i = s0; i < s1; i++) {
        int s = g_esrc[i];
        const float* rp = g_y2 + (size_t)s * NC;
        a0 += __ldg(rp + l);
        if (l < 8) a1 += __ldg(rp + 32 + l);
    }
    {
        const float* rp = g_y2 + (size_t)c * NC;
        a0 += __ldg(rp + l);
        if (l < 8) a1 += __ldg(rp + 32 + l);
    }
    float d  = g_dinv[c];
    float v0 = d * a0 + __ldg(b2 + l);
    float v1 = (l < 8) ? (d * a1 + __ldg(b2 + 32 + l)) : -3.4e38f;

    float m = fmaxf(v0, v1);
#pragma unroll
    for (int o = 16; o; o >>= 1) m = fmaxf(m, __shfl_xor_sync(0xffffffffu, m, o));
    float e = expf(v0 - m) + ((l < 8) ? expf(v1 - m) : 0.f);
#pragma unroll
    for (int o = 16; o; o >>= 1) e += __shfl_xor_sync(0xffffffffu, e, o);
    float lse = m + logf(e);

    out[(size_t)c * NC + l] = v0 - lse;
    if (l < 8) out[(size_t)c * NC + 32 + l] = v1 - lse;
}

// ---------------- launch ----------------
extern "C" void kernel_launch(void* const* d_in, const int* in_sizes, int n_in,
                              void* d_out, int out_size) {
    const float* x   = (const float*)d_in[0];
    const void*  ei  = d_in[1];               // edge_index: int32 OR int64 (detected)
    const float* W1  = (const float*)d_in[2];
    const float* b1  = (const float*)d_in[3];
    const float* W2  = (const float*)d_in[4];
    const float* b2  = (const float*)d_in[5];
    float*       out = (float*)d_out;

    int M = in_sizes[0] / FIN;   // 100000
    int E = in_sizes[1] / 2;     // 3200000 (element count is dtype-independent)

    int tb = 256;
    int gM = (M + tb - 1) / tb;
    int gE = (E + tb - 1) / tb;

    // dtype detection + degree + dinv
    k_detect<<<1, 32>>>(ei, M);
    k_zero_deg<<<gM, tb>>>(M);
    k_hist<<<gE, tb>>>(ei, E);
    k_dinv<<<gM, tb>>>(M);

    // CSR: scan + fill
    int NB = (M + 1023) / 1024;          // 98
    k_scan1<<<NB, 256>>>(M);
    k_scan2<<<1, 128>>>(NB);
    k_scan3<<<gM, tb>>>(M, E);
    k_fill<<<gE, tb>>>(ei, E);

    // layer 1
    dim3 g1((M + 127) / 128, HID / 128);
    k_sgemm1<<<g1, 256>>>(x, W1, M);
    int gW = ((M * 32) + tb - 1) / tb;   // one warp per node
    k_agg1<<<gW, tb>>>(b1, M);

    // layer 2 + softmax
    k_sgemm2<<<(M + 255) / 256, 256>>>(W2, M);
    k_agg2_softmax<<<gW, tb>>>(b2, out, M);
}

// round 8
// speedup vs baseline: 1.3415x; 1.3415x over previous
#include <cuda_runtime.h>
#include <cuda_bf16.h>
#include <math.h>
#include <stdint.h>

#define NMAX 100000
#define EMAX 3200000
#define FIN  512
#define HID  256
#define NC   40

// ---------------- device scratch (static: no allocation) ----------------
__device__ int   g_is64;                  // edge_index dtype flag (1 = int64)
__device__ int   g_deg[NMAX];
__device__ float g_dinv[NMAX];
__device__ int   g_off[NMAX + 1];
__device__ int   g_cur[NMAX];
__device__ int   g_bsum[128];
__device__ int   g_bbase[128];
__device__ int   g_esrc[EMAX];
__device__ __align__(16) __nv_bfloat16 g_w1hi[HID * FIN];  // W1^T [256][512] bf16 hi
__device__ __align__(16) __nv_bfloat16 g_w1lo[HID * FIN];  // W1^T [256][512] bf16 lo
__device__ __align__(16) float g_y1[(size_t)NMAX * HID];   // dinv-scaled x@W1
__device__ __align__(16) float g_h [(size_t)NMAX * HID];   // layer-1 output (relu)
__device__ __align__(16) float g_y2[(size_t)NMAX * NC];    // dinv-scaled h@W2

// ---------------- helpers ----------------
__device__ __forceinline__ uint32_t smem_to_u32(const void* p) {
    uint32_t a;
    asm("{ .reg .u64 t; cvta.to.shared.u64 t, %1; cvt.u32.u64 %0, t; }"
        : "=r"(a) : "l"(p));
    return a;
}
__device__ __forceinline__ uint32_t sw128(uint32_t off) {
    return off ^ ((off >> 3) & 0x70);
}
__device__ __forceinline__ void ldm_x4(uint32_t& r0, uint32_t& r1,
                                       uint32_t& r2, uint32_t& r3, uint32_t a) {
    asm volatile("ldmatrix.sync.aligned.m8n8.x4.shared.b16 {%0,%1,%2,%3}, [%4];"
                 : "=r"(r0), "=r"(r1), "=r"(r2), "=r"(r3) : "r"(a));
}
__device__ __forceinline__ void ldm_x2(uint32_t& r0, uint32_t& r1, uint32_t a) {
    asm volatile("ldmatrix.sync.aligned.m8n8.x2.shared.b16 {%0,%1}, [%2];"
                 : "=r"(r0), "=r"(r1) : "r"(a));
}
__device__ __forceinline__ void mma_bf16(float* c, const uint32_t* a,
                                         const uint32_t* b) {
    asm volatile(
        "mma.sync.aligned.m16n8k16.row.col.f32.bf16.bf16.f32 "
        "{%0,%1,%2,%3}, {%4,%5,%6,%7}, {%8,%9}, {%0,%1,%2,%3};"
        : "+f"(c[0]), "+f"(c[1]), "+f"(c[2]), "+f"(c[3])
        : "r"(a[0]), "r"(a[1]), "r"(a[2]), "r"(a[3]), "r"(b[0]), "r"(b[1]));
}

// ---------------- edge index access (dtype-robust) ----------------
__device__ __forceinline__ int edge_at(const void* ei, int i) {
    if (g_is64) return (int)((const long long*)ei)[i];
    return ((const int*)ei)[i];
}

__global__ void k_detect(const void* ei, int n) {
    if (blockIdx.x == 0 && threadIdx.x == 0) {
        const int* w = (const int*)ei;
        int is64 = 1;
        for (int i = 0; i < 64; i++) {
            int lo = w[2 * i], hi = w[2 * i + 1];
            if (hi != 0 || lo < 0 || lo >= n) { is64 = 0; break; }
        }
        g_is64 = is64;
    }
}

// ---------------- small utility kernels ----------------
__global__ void k_zero_deg(int n) {
    int i = blockIdx.x * blockDim.x + threadIdx.x;
    if (i < n) g_deg[i] = 0;
}

__global__ void k_hist(const void* __restrict__ ei, int E) {
    int e = blockIdx.x * blockDim.x + threadIdx.x;
    if (e < E) atomicAdd(&g_deg[edge_at(ei, E + e)], 1);
}

__global__ void k_dinv(int n) {
    int i = blockIdx.x * blockDim.x + threadIdx.x;
    if (i < n) g_dinv[i] = rsqrtf((float)(g_deg[i] + 1));   // +1 self loop
}

// W1 [512][256] fp32 -> g_w1hi/g_w1lo [256][512] bf16 (K-major, transposed)
__global__ void k_wprep(const float* __restrict__ W1) {
    int idx = blockIdx.x * blockDim.x + threadIdx.x;   // 0 .. 256*512-1
    if (idx < HID * FIN) {
        int n = idx >> 9, k = idx & 511;
        float w = W1[(size_t)k * HID + n];
        __nv_bfloat16 hi = __float2bfloat16(w);
        __nv_bfloat16 lo = __float2bfloat16(w - __bfloat162float(hi));
        g_w1hi[idx] = hi;
        g_w1lo[idx] = lo;
    }
}

// ---------------- exclusive scan of g_deg -> g_off (3 kernels) ----------------
__global__ void k_scan1(int n) {
    __shared__ int sdata[256];
    int b = blockIdx.x, t = threadIdx.x;
    int base = b * 1024 + t * 4;
    int v0 = (base + 0 < n) ? g_deg[base + 0] : 0;
    int v1 = (base + 1 < n) ? g_deg[base + 1] : 0;
    int v2 = (base + 2 < n) ? g_deg[base + 2] : 0;
    int v3 = (base + 3 < n) ? g_deg[base + 3] : 0;
    int tsum = v0 + v1 + v2 + v3;
    sdata[t] = tsum;
    __syncthreads();
    for (int off = 1; off < 256; off <<= 1) {
        int x = 0;
        if (t >= off) x = sdata[t - off];
        __syncthreads();
        sdata[t] += x;
        __syncthreads();
    }
    int run = sdata[t] - tsum;
    if (base + 0 < n) { g_off[base + 0] = run; run += v0; }
    if (base + 1 < n) { g_off[base + 1] = run; run += v1; }
    if (base + 2 < n) { g_off[base + 2] = run; run += v2; }
    if (base + 3 < n) { g_off[base + 3] = run; }
    if (t == 255) g_bsum[b] = sdata[255];
}

__global__ void k_scan2(int nb) {
    __shared__ int s[128];
    int t = threadIdx.x;
    int v = (t < nb) ? g_bsum[t] : 0;
    s[t] = v;
    __syncthreads();
    for (int off = 1; off < 128; off <<= 1) {
        int x = 0;
        if (t >= off) x = s[t - off];
        __syncthreads();
        s[t] += x;
        __syncthreads();
    }
    g_bbase[t] = s[t] - v;
}

__global__ void k_scan3(int n, int E) {
    int i = blockIdx.x * blockDim.x + threadIdx.x;
    if (i < n) {
        int o = g_off[i] + g_bbase[i >> 10];
        g_off[i] = o;
        g_cur[i] = o;
    }
    if (i == 0) g_off[n] = E;
}

__global__ void k_fill(const void* __restrict__ ei, int E) {
    int e = blockIdx.x * blockDim.x + threadIdx.x;
    if (e < E) {
        int r = edge_at(ei, e);          // source
        int c = edge_at(ei, E + e);      // target
        int pos = atomicAdd(&g_cur[c], 1);
        g_esrc[pos] = r;
    }
}

// ---------------- GEMM1 (mma.sync bf16 3-term): y1 = dinv .* (x @ W1) ----------------
// CTA tile 128x128, 8 warps (2x4), warp tile 64x32, BK=64 bf16.
// SW128-swizzled smem rows of 128B (64 bf16) -> conflict-free ldmatrix.
#define G1_AHI 0
#define G1_ALO 16384
#define G1_BHI 32768
#define G1_BLO 49152
#define G1_TOT 65536

__global__ __launch_bounds__(256) void k_mma_gemm1(const float* __restrict__ A, int M) {
    extern __shared__ char smem[];
    uint32_t sb = smem_to_u32(smem);
    int tid  = threadIdx.x;
    int wid  = tid >> 5;
    int lane = tid & 31;
    int row0 = blockIdx.x * 128;
    int col0 = blockIdx.y * 128;
    int warp_m = wid & 1;          // 0/1 -> 64 rows each
    int warp_n = wid >> 1;         // 0..3 -> 32 cols each

    // ldmatrix per-lane address components
    int a_sel   = lane >> 3;                     // 0..3
    int a_row16 = (lane & 7) + ((a_sel & 1) << 3);
    int a_seg   = a_sel >> 1;                    // 0/1 (k half)
    int b_sel   = (lane >> 3) & 1;               // 0/1 (k half)
    int b_row   = lane & 7;

    float acc[4][4][4];
#pragma unroll
    for (int mi = 0; mi < 4; mi++)
#pragma unroll
        for (int ni = 0; ni < 4; ni++)
#pragma unroll
            for (int q = 0; q < 4; q++) acc[mi][ni][q] = 0.f;

    const char* w1hi = (const char*)g_w1hi;
    const char* w1lo = (const char*)g_w1lo;

    for (int c = 0; c < FIN / 64; c++) {          // 8 chunks of K=64
        int k0 = c * 64;
        // ---- load A 128x64 fp32 -> bf16 hi/lo, SW128 ----
#pragma unroll
        for (int i = 0; i < 8; i++) {
            int li = tid + i * 256;
            int r = li >> 4, c4 = li & 15;
            int gr = row0 + r;
            float4 v = (gr < M)
                ? *(const float4*)(A + (size_t)gr * FIN + k0 + c4 * 4)
                : make_float4(0.f, 0.f, 0.f, 0.f);
            __nv_bfloat162 h01 = make_bfloat162(__float2bfloat16(v.x), __float2bfloat16(v.y));
            __nv_bfloat162 h23 = make_bfloat162(__float2bfloat16(v.z), __float2bfloat16(v.w));
            __nv_bfloat162 l01 = make_bfloat162(
                __float2bfloat16(v.x - __bfloat162float(h01.x)),
                __float2bfloat16(v.y - __bfloat162float(h01.y)));
            __nv_bfloat162 l23 = make_bfloat162(
                __float2bfloat16(v.z - __bfloat162float(h23.x)),
                __float2bfloat16(v.w - __bfloat162float(h23.y)));
            uint32_t off = sw128((uint32_t)(r * 128 + c4 * 8));
            *(__nv_bfloat162*)(smem + G1_AHI + off)     = h01;
            *(__nv_bfloat162*)(smem + G1_AHI + off + 4) = h23;
            *(__nv_bfloat162*)(smem + G1_ALO + off)     = l01;
            *(__nv_bfloat162*)(smem + G1_ALO + off + 4) = l23;
        }
        // ---- load B (W1^T) 128 n-rows x 64 k bf16 per term, SW128 ----
#pragma unroll
        for (int i = 0; i < 4; i++) {
            int li = tid + i * 256;                // 0..1023
            int r = li >> 3, seg = li & 7;
            size_t gsrc = (size_t)(col0 + r) * (FIN * 2) + (size_t)k0 * 2 + seg * 16;
            uint32_t off = sw128((uint32_t)(r * 128 + seg * 16));
            *(uint4*)(smem + G1_BHI + off) = *(const uint4*)(w1hi + gsrc);
            *(uint4*)(smem + G1_BLO + off) = *(const uint4*)(w1lo + gsrc);
        }
        __syncthreads();

        // ---- compute: 4 k16 steps ----
#pragma unroll
        for (int ks = 0; ks < 4; ks++) {
            uint32_t ahi[4][4], alo[4][4], bhi[4][2], blo[4][2];
#pragma unroll
            for (int mi = 0; mi < 4; mi++) {
                int row = warp_m * 64 + mi * 16 + a_row16;
                uint32_t off = sw128((uint32_t)(row * 128 + (ks * 2 + a_seg) * 16));
                ldm_x4(ahi[mi][0], ahi[mi][1], ahi[mi][2], ahi[mi][3],
                       sb + G1_AHI + off);
                ldm_x4(alo[mi][0], alo[mi][1], alo[mi][2], alo[mi][3],
                       sb + G1_ALO + off);
            }
#pragma unroll
            for (int ni = 0; ni < 4; ni++) {
                int rn = warp_n * 32 + ni * 8 + b_row;
                uint32_t off = sw128((uint32_t)(rn * 128 + (ks * 2 + b_sel) * 16));
                ldm_x2(bhi[ni][0], bhi[ni][1], sb + G1_BHI + off);
                ldm_x2(blo[ni][0], blo[ni][1], sb + G1_BLO + off);
            }
#pragma unroll
            for (int mi = 0; mi < 4; mi++)
#pragma unroll
                for (int ni = 0; ni < 4; ni++) {
                    mma_bf16(acc[mi][ni], ahi[mi], bhi[ni]);
                    mma_bf16(acc[mi][ni], ahi[mi], blo[ni]);
                    mma_bf16(acc[mi][ni], alo[mi], bhi[ni]);
                }
        }
        __syncthreads();
    }

    // ---- epilogue: dinv scale + store ----
#pragma unroll
    for (int mi = 0; mi < 4; mi++) {
        int r0 = row0 + warp_m * 64 + mi * 16 + (lane >> 2);
        int r1 = r0 + 8;
        float d0 = (r0 < M) ? g_dinv[r0] : 0.f;
        float d1 = (r1 < M) ? g_dinv[r1] : 0.f;
#pragma unroll
        for (int ni = 0; ni < 4; ni++) {
            int cc = col0 + warp_n * 32 + ni * 8 + (lane & 3) * 2;
            if (r0 < M) {
                float2 o = make_float2(d0 * acc[mi][ni][0], d0 * acc[mi][ni][1]);
                *(float2*)&g_y1[(size_t)r0 * HID + cc] = o;
            }
            if (r1 < M) {
                float2 o = make_float2(d1 * acc[mi][ni][2], d1 * acc[mi][ni][3]);
                *(float2*)&g_y1[(size_t)r1 * HID + cc] = o;
            }
        }
    }
}

// ---------------- Aggregation 1: h = relu(dinv*(sum y1[src] + y1[c]) + b1) ----------------
__global__ void k_agg1(const float* __restrict__ b1, int M) {
    int gid  = blockIdx.x * blockDim.x + threadIdx.x;
    int c    = gid >> 5;
    int lane = gid & 31;
    if (c >= M) return;

    const float4* Y = (const float4*)g_y1;
    float4 a0 = make_float4(0.f, 0.f, 0.f, 0.f);
    float4 a1 = make_float4(0.f, 0.f, 0.f, 0.f);

    int s0 = g_off[c], s1 = g_off[c + 1];
    for (int i = s0; i < s1; i++) {
        int s = g_esrc[i];
        const float4* rp = Y + (size_t)s * 64;
        float4 v0 = __ldg(rp + lane);
        float4 v1 = __ldg(rp + lane + 32);
        a0.x += v0.x; a0.y += v0.y; a0.z += v0.z; a0.w += v0.w;
        a1.x += v1.x; a1.y += v1.y; a1.z += v1.z; a1.w += v1.w;
    }
    {   // self loop
        const float4* rp = Y + (size_t)c * 64;
        float4 v0 = __ldg(rp + lane);
        float4 v1 = __ldg(rp + lane + 32);
        a0.x += v0.x; a0.y += v0.y; a0.z += v0.z; a0.w += v0.w;
        a1.x += v1.x; a1.y += v1.y; a1.z += v1.z; a1.w += v1.w;
    }
    float d = g_dinv[c];
    float4 bb0 = make_float4(__ldg(b1 + lane * 4 + 0), __ldg(b1 + lane * 4 + 1),
                             __ldg(b1 + lane * 4 + 2), __ldg(b1 + lane * 4 + 3));
    float4 bb1 = make_float4(__ldg(b1 + 128 + lane * 4 + 0), __ldg(b1 + 128 + lane * 4 + 1),
                             __ldg(b1 + 128 + lane * 4 + 2), __ldg(b1 + 128 + lane * 4 + 3));
    float4 o0, o1;
    o0.x = fmaxf(d * a0.x + bb0.x, 0.f);
    o0.y = fmaxf(d * a0.y + bb0.y, 0.f);
    o0.z = fmaxf(d * a0.z + bb0.z, 0.f);
    o0.w = fmaxf(d * a0.w + bb0.w, 0.f);
    o1.x = fmaxf(d * a1.x + bb1.x, 0.f);
    o1.y = fmaxf(d * a1.y + bb1.y, 0.f);
    o1.z = fmaxf(d * a1.z + bb1.z, 0.f);
    o1.w = fmaxf(d * a1.w + bb1.w, 0.f);
    float4* H = (float4*)g_h;
    H[(size_t)c * 64 + lane]      = o0;
    H[(size_t)c * 64 + lane + 32] = o1;
}

// ---------------- GEMM2: y2 = dinv .* (h @ W2)   [M,256]x[256,40] ----------------
__global__ __launch_bounds__(256) void k_sgemm2(const float* __restrict__ W2, int M) {
    __shared__ __align__(16) float hs[16][260];
    __shared__ __align__(16) float ws[16 * NC];
    int tid = threadIdx.x;
    int R0  = blockIdx.x * 256;
    int kv  = tid & 3;
    int rld = tid >> 2;
    int cg  = tid & 3;
    int rq  = tid >> 2;

    float acc[4][10];
#pragma unroll
    for (int i = 0; i < 4; i++)
#pragma unroll
        for (int j = 0; j < 10; j++) acc[i][j] = 0.f;

    for (int k0 = 0; k0 < HID; k0 += 16) {
#pragma unroll
        for (int p = 0; p < 4; p++) {
            int rr = rld + p * 64;
            int gr = R0 + rr;
            float4 v = (gr < M)
                ? *(const float4*)&g_h[(size_t)gr * HID + k0 + kv * 4]
                : make_float4(0.f, 0.f, 0.f, 0.f);
            hs[kv * 4 + 0][rr] = v.x;
            hs[kv * 4 + 1][rr] = v.y;
            hs[kv * 4 + 2][rr] = v.z;
            hs[kv * 4 + 3][rr] = v.w;
        }
        if (tid < 160) {
            const float* wp = W2 + (size_t)k0 * NC + tid * 4;
            ws[tid * 4 + 0] = wp[0];
            ws[tid * 4 + 1] = wp[1];
            ws[tid * 4 + 2] = wp[2];
            ws[tid * 4 + 3] = wp[3];
        }
        __syncthreads();

#pragma unroll
        for (int kk = 0; kk < 16; kk++) {
            float h0 = hs[kk][rq * 4 + 0];
            float h1 = hs[kk][rq * 4 + 1];
            float h2 = hs[kk][rq * 4 + 2];
            float h3 = hs[kk][rq * 4 + 3];
#pragma unroll
            for (int j = 0; j < 10; j++) {
                float w = ws[kk * NC + cg * 10 + j];
                acc[0][j] += h0 * w;
                acc[1][j] += h1 * w;
                acc[2][j] += h2 * w;
                acc[3][j] += h3 * w;
            }
        }
        __syncthreads();
    }

#pragma unroll
    for (int i = 0; i < 4; i++) {
        int r = R0 + rq * 4 + i;
        if (r < M) {
            float d = g_dinv[r];
            float* yp = &g_y2[(size_t)r * NC + cg * 10];
#pragma unroll
            for (int j = 0; j < 10; j++) yp[j] = d * acc[i][j];
        }
    }
}

// ---------------- Aggregation 2 + bias + log_softmax ----------------
__global__ void k_agg2_softmax(const float* __restrict__ b2,
                               float* __restrict__ out, int M) {
    int gid  = blockIdx.x * blockDim.x + threadIdx.x;
    int c    = gid >> 5;
    int l    = gid & 31;
    if (c >= M) return;

    float a0 = 0.f, a1 = 0.f;
    int s0 = g_off[c], s1 = g_off[c + 1];
    for (int i = s0; i < s1; i++) {
        int s = g_esrc[i];
        const float* rp = g_y2 + (size_t)s * NC;
        a0 += __ldg(rp + l);
        if (l < 8) a1 += __ldg(rp + 32 + l);
    }
    {
        const float* rp = g_y2 + (size_t)c * NC;
        a0 += __ldg(rp + l);
        if (l < 8) a1 += __ldg(rp + 32 + l);
    }
    float d  = g_dinv[c];
    float v0 = d * a0 + __ldg(b2 + l);
    float v1 = (l < 8) ? (d * a1 + __ldg(b2 + 32 + l)) : -3.4e38f;

    float m = fmaxf(v0, v1);
#pragma unroll
    for (int o = 16; o; o >>= 1) m = fmaxf(m, __shfl_xor_sync(0xffffffffu, m, o));
    float e = expf(v0 - m) + ((l < 8) ? expf(v1 - m) : 0.f);
#pragma unroll
    for (int o = 16; o; o >>= 1) e += __shfl_xor_sync(0xffffffffu, e, o);
    float lse = m + logf(e);

    out[(size_t)c * NC + l] = v0 - lse;
    if (l < 8) out[(size_t)c * NC + 32 + l] = v1 - lse;
}

// ---------------- launch ----------------
extern "C" void kernel_launch(void* const* d_in, const int* in_sizes, int n_in,
                              void* d_out, int out_size) {
    const float* x   = (const float*)d_in[0];
    const void*  ei  = d_in[1];               // edge_index: int32 OR int64 (detected)
    const float* W1  = (const float*)d_in[2];
    const float* b1  = (const float*)d_in[3];
    const float* W2  = (const float*)d_in[4];
    const float* b2  = (const float*)d_in[5];
    float*       out = (float*)d_out;

    int M = in_sizes[0] / FIN;   // 100000
    int E = in_sizes[1] / 2;     // 3200000

    int tb = 256;
    int gM = (M + tb - 1) / tb;
    int gE = (E + tb - 1) / tb;

    // dtype detection + degree + dinv + W1 prep
    k_detect<<<1, 32>>>(ei, M);
    k_zero_deg<<<gM, tb>>>(M);
    k_hist<<<gE, tb>>>(ei, E);
    k_dinv<<<gM, tb>>>(M);
    k_wprep<<<(HID * FIN + 255) / 256, 256>>>(W1);

    // CSR: scan + fill
    int NB = (M + 1023) / 1024;          // 98
    k_scan1<<<NB, 256>>>(M);
    k_scan2<<<1, 128>>>(NB);
    k_scan3<<<gM, tb>>>(M, E);
    k_fill<<<gE, tb>>>(ei, E);

    // layer 1: tensor-core GEMM (mma.sync) + CSR gather
    cudaFuncSetAttribute(k_mma_gemm1, cudaFuncAttributeMaxDynamicSharedMemorySize,
                         G1_TOT);
    dim3 g1((M + 127) / 128, 2);
    k_mma_gemm1<<<g1, 256, G1_TOT>>>(x, M);
    int gW = ((M * 32) + tb - 1) / tb;   // one warp per node
    k_agg1<<<gW, tb>>>(b1, M);

    // layer 2 + softmax
    k_sgemm2<<<(M + 255) / 256, 256>>>(W2, M);
    k_agg2_softmax<<<gW, tb>>>(b2, out, M);
}

// round 10
// speedup vs baseline: 2.0722x; 1.5447x over previous
#include <cuda_runtime.h>
#include <cuda_fp16.h>
#include <cuda_bf16.h>
#include <math.h>
#include <stdint.h>

#define NMAX 100000
#define EMAX 3200000
#define FIN  512
#define HID  256
#define NC   40

// ---------------- device scratch (static: no allocation) ----------------
__device__ int   g_is64;                  // edge_index dtype flag (1 = int64)
__device__ int   g_deg[NMAX];
__device__ float g_dinv[NMAX];
__device__ int   g_off[NMAX + 1];
__device__ int   g_cur[NMAX];
__device__ int   g_bsum[128];
__device__ int   g_bbase[128];
__device__ int   g_esrc[EMAX];
__device__ __align__(16) __nv_bfloat16 g_w1hi[HID * FIN];  // W1^T [256][512] bf16 hi
__device__ __align__(16) __nv_bfloat16 g_w1lo[HID * FIN];  // W1^T [256][512] bf16 lo
__device__ __align__(16) __half g_y1h[(size_t)NMAX * HID]; // dinv-scaled x@W1 (fp16 msgs)
__device__ __align__(16) float  g_h [(size_t)NMAX * HID];  // layer-1 output (relu, fp32)
__device__ __align__(16) __half g_y2h[(size_t)NMAX * NC];  // dinv-scaled h@W2 (fp16 msgs)

// ---------------- helpers ----------------
__device__ __forceinline__ uint32_t smem_to_u32(const void* p) {
    uint32_t a;
    asm("{ .reg .u64 t; cvta.to.shared.u64 t, %1; cvt.u32.u64 %0, t; }"
        : "=r"(a) : "l"(p));
    return a;
}
__device__ __forceinline__ uint32_t sw128(uint32_t off) {
    return off ^ ((off >> 3) & 0x70);
}
__device__ __forceinline__ void ldm_x4(uint32_t& r0, uint32_t& r1,
                                       uint32_t& r2, uint32_t& r3, uint32_t a) {
    asm volatile("ldmatrix.sync.aligned.m8n8.x4.shared.b16 {%0,%1,%2,%3}, [%4];"
                 : "=r"(r0), "=r"(r1), "=r"(r2), "=r"(r3) : "r"(a));
}
__device__ __forceinline__ void ldm_x2(uint32_t& r0, uint32_t& r1, uint32_t a) {
    asm volatile("ldmatrix.sync.aligned.m8n8.x2.shared.b16 {%0,%1}, [%2];"
                 : "=r"(r0), "=r"(r1) : "r"(a));
}
__device__ __forceinline__ void mma_bf16(float* c, const uint32_t* a,
                                         const uint32_t* b) {
    asm volatile(
        "mma.sync.aligned.m16n8k16.row.col.f32.bf16.bf16.f32 "
        "{%0,%1,%2,%3}, {%4,%5,%6,%7}, {%8,%9}, {%0,%1,%2,%3};"
        : "+f"(c[0]), "+f"(c[1]), "+f"(c[2]), "+f"(c[3])
        : "r"(a[0]), "r"(a[1]), "r"(a[2]), "r"(a[3]), "r"(b[0]), "r"(b[1]));
}

// ---------------- edge index access (dtype-robust) ----------------
__device__ __forceinline__ int edge_at(const void* ei, int i) {
    if (g_is64) return (int)((const long long*)ei)[i];
    return ((const int*)ei)[i];
}

__global__ void k_detect(const void* ei, int n) {
    if (blockIdx.x == 0 && threadIdx.x == 0) {
        const int* w = (const int*)ei;
        int is64 = 1;
        for (int i = 0; i < 64; i++) {
            int lo = w[2 * i], hi = w[2 * i + 1];
            if (hi != 0 || lo < 0 || lo >= n) { is64 = 0; break; }
        }
        g_is64 = is64;
    }
}

// ---------------- small utility kernels ----------------
__global__ void k_zero_deg(int n) {
    int i = blockIdx.x * blockDim.x + threadIdx.x;
    if (i < n) g_deg[i] = 0;
}

__global__ void k_hist(const void* __restrict__ ei, int E) {
    int e = blockIdx.x * blockDim.x + threadIdx.x;
    if (e < E) atomicAdd(&g_deg[edge_at(ei, E + e)], 1);
}

__global__ void k_dinv(int n) {
    int i = blockIdx.x * blockDim.x + threadIdx.x;
    if (i < n) g_dinv[i] = rsqrtf((float)(g_deg[i] + 1));   // +1 self loop
}

// W1 [512][256] fp32 -> g_w1hi/g_w1lo [256][512] bf16 (K-major, transposed)
__global__ void k_wprep(const float* __restrict__ W1) {
    int idx = blockIdx.x * blockDim.x + threadIdx.x;   // 0 .. 256*512-1
    if (idx < HID * FIN) {
        int n = idx >> 9, k = idx & 511;
        float w = W1[(size_t)k * HID + n];
        __nv_bfloat16 hi = __float2bfloat16(w);
        __nv_bfloat16 lo = __float2bfloat16(w - __bfloat162float(hi));
        g_w1hi[idx] = hi;
        g_w1lo[idx] = lo;
    }
}

// ---------------- exclusive scan of g_deg -> g_off (3 kernels) ----------------
__global__ void k_scan1(int n) {
    __shared__ int sdata[256];
    int b = blockIdx.x, t = threadIdx.x;
    int base = b * 1024 + t * 4;
    int v0 = (base + 0 < n) ? g_deg[base + 0] : 0;
    int v1 = (base + 1 < n) ? g_deg[base + 1] : 0;
    int v2 = (base + 2 < n) ? g_deg[base + 2] : 0;
    int v3 = (base + 3 < n) ? g_deg[base + 3] : 0;
    int tsum = v0 + v1 + v2 + v3;
    sdata[t] = tsum;
    __syncthreads();
    for (int off = 1; off < 256; off <<= 1) {
        int x = 0;
        if (t >= off) x = sdata[t - off];
        __syncthreads();
        sdata[t] += x;
        __syncthreads();
    }
    int run = sdata[t] - tsum;
    if (base + 0 < n) { g_off[base + 0] = run; run += v0; }
    if (base + 1 < n) { g_off[base + 1] = run; run += v1; }
    if (base + 2 < n) { g_off[base + 2] = run; run += v2; }
    if (base + 3 < n) { g_off[base + 3] = run; }
    if (t == 255) g_bsum[b] = sdata[255];
}

__global__ void k_scan2(int nb) {
    __shared__ int s[128];
    int t = threadIdx.x;
    int v = (t < nb) ? g_bsum[t] : 0;
    s[t] = v;
    __syncthreads();
    for (int off = 1; off < 128; off <<= 1) {
        int x = 0;
        if (t >= off) x = s[t - off];
        __syncthreads();
        s[t] += x;
        __syncthreads();
    }
    g_bbase[t] = s[t] - v;
}

__global__ void k_scan3(int n, int E) {
    int i = blockIdx.x * blockDim.x + threadIdx.x;
    if (i < n) {
        int o = g_off[i] + g_bbase[i >> 10];
        g_off[i] = o;
        g_cur[i] = o;
    }
    if (i == 0) g_off[n] = E;
}

__global__ void k_fill(const void* __restrict__ ei, int E) {
    int e = blockIdx.x * blockDim.x + threadIdx.x;
    if (e < E) {
        int r = edge_at(ei, e);          // source
        int c = edge_at(ei, E + e);      // target
        int pos = atomicAdd(&g_cur[c], 1);
        g_esrc[pos] = r;
    }
}

// ---------------- GEMM1 (mma.sync bf16 3-term, double-buffered) ----------------
// CTA tile 128x128, 8 warps (2x4), warp tile 64x32, BK=64 bf16.
// Two 64KB smem stages; prefetch chunk c+1 in regs while computing chunk c.
#define G1_AHI 0
#define G1_ALO 16384
#define G1_BHI 32768
#define G1_BLO 49152
#define G1_STAGE 65536
#define G1_TOT (2 * G1_STAGE)

__global__ __launch_bounds__(256, 1) void k_mma_gemm1(const float* __restrict__ A, int M) {
    extern __shared__ char smem[];
    uint32_t sb = smem_to_u32(smem);
    int tid  = threadIdx.x;
    int wid  = tid >> 5;
    int lane = tid & 31;
    int row0 = blockIdx.x * 128;
    int col0 = blockIdx.y * 128;
    int warp_m = wid & 1;          // 0/1 -> 64 rows each
    int warp_n = wid >> 1;         // 0..3 -> 32 cols each

    // ldmatrix per-lane address components
    int a_sel   = lane >> 3;                     // 0..3
    int a_row16 = (lane & 7) + ((a_sel & 1) << 3);
    int a_seg   = a_sel >> 1;                    // 0/1 (k half)
    int b_sel   = (lane >> 3) & 1;               // 0/1 (k half)
    int b_row   = lane & 7;

    float acc[4][4][4];
#pragma unroll
    for (int mi = 0; mi < 4; mi++)
#pragma unroll
        for (int ni = 0; ni < 4; ni++)
#pragma unroll
            for (int q = 0; q < 4; q++) acc[mi][ni][q] = 0.f;

    const char* w1hi = (const char*)g_w1hi;
    const char* w1lo = (const char*)g_w1lo;

    // ---- prefetch registers ----
    float4 av[8];
    uint4  bhv[4], blv[4];

    auto load_regs = [&](int k0) {
#pragma unroll
        for (int i = 0; i < 8; i++) {
            int li = tid + i * 256;
            int r = li >> 4, c4 = li & 15;
            int gr = row0 + r;
            av[i] = (gr < M)
                ? *(const float4*)(A + (size_t)gr * FIN + k0 + c4 * 4)
                : make_float4(0.f, 0.f, 0.f, 0.f);
        }
#pragma unroll
        for (int i = 0; i < 4; i++) {
            int li = tid + i * 256;                // 0..1023
            int r = li >> 3, seg = li & 7;
            size_t gsrc = (size_t)(col0 + r) * (FIN * 2) + (size_t)k0 * 2 + seg * 16;
            bhv[i] = *(const uint4*)(w1hi + gsrc);
            blv[i] = *(const uint4*)(w1lo + gsrc);
        }
    };

    auto store_smem = [&](int so) {
#pragma unroll
        for (int i = 0; i < 8; i++) {
            int li = tid + i * 256;
            int r = li >> 4, c4 = li & 15;
            float4 v = av[i];
            __nv_bfloat162 h01 = make_bfloat162(__float2bfloat16(v.x), __float2bfloat16(v.y));
            __nv_bfloat162 h23 = make_bfloat162(__float2bfloat16(v.z), __float2bfloat16(v.w));
            __nv_bfloat162 l01 = make_bfloat162(
                __float2bfloat16(v.x - __bfloat162float(h01.x)),
                __float2bfloat16(v.y - __bfloat162float(h01.y)));
            __nv_bfloat162 l23 = make_bfloat162(
                __float2bfloat16(v.z - __bfloat162float(h23.x)),
                __float2bfloat16(v.w - __bfloat162float(h23.y)));
            uint32_t off = sw128((uint32_t)(r * 128 + c4 * 8));
            *(__nv_bfloat162*)(smem + so + G1_AHI + off)     = h01;
            *(__nv_bfloat162*)(smem + so + G1_AHI + off + 4) = h23;
            *(__nv_bfloat162*)(smem + so + G1_ALO + off)     = l01;
            *(__nv_bfloat162*)(smem + so + G1_ALO + off + 4) = l23;
        }
#pragma unroll
        for (int i = 0; i < 4; i++) {
            int li = tid + i * 256;
            int r = li >> 3, seg = li & 7;
            uint32_t off = sw128((uint32_t)(r * 128 + seg * 16));
            *(uint4*)(smem + so + G1_BHI + off) = bhv[i];
            *(uint4*)(smem + so + G1_BLO + off) = blv[i];
        }
    };

    load_regs(0);
    store_smem(0);
    __syncthreads();

    for (int c = 0; c < FIN / 64; c++) {          // 8 chunks of K=64
        int cur = (c & 1) * G1_STAGE;
        if (c < 7) load_regs((c + 1) * 64);        // global prefetch (overlaps mma)

        // ---- compute: 4 k16 steps from stage cur ----
#pragma unroll
        for (int ks = 0; ks < 4; ks++) {
            uint32_t ahi[4][4], alo[4][4], bhi[4][2], blo[4][2];
#pragma unroll
            for (int mi = 0; mi < 4; mi++) {
                int row = warp_m * 64 + mi * 16 + a_row16;
                uint32_t off = sw128((uint32_t)(row * 128 + (ks * 2 + a_seg) * 16));
                ldm_x4(ahi[mi][0], ahi[mi][1], ahi[mi][2], ahi[mi][3],
                       sb + cur + G1_AHI + off);
                ldm_x4(alo[mi][0], alo[mi][1], alo[mi][2], alo[mi][3],
                       sb + cur + G1_ALO + off);
            }
#pragma unroll
            for (int ni = 0; ni < 4; ni++) {
                int rn = warp_n * 32 + ni * 8 + b_row;
                uint32_t off = sw128((uint32_t)(rn * 128 + (ks * 2 + b_sel) * 16));
                ldm_x2(bhi[ni][0], bhi[ni][1], sb + cur + G1_BHI + off);
                ldm_x2(blo[ni][0], blo[ni][1], sb + cur + G1_BLO + off);
            }
#pragma unroll
            for (int mi = 0; mi < 4; mi++)
#pragma unroll
                for (int ni = 0; ni < 4; ni++) {
                    mma_bf16(acc[mi][ni], ahi[mi], bhi[ni]);
                    mma_bf16(acc[mi][ni], ahi[mi], blo[ni]);
                    mma_bf16(acc[mi][ni], alo[mi], bhi[ni]);
                }
        }

        if (c < 7) store_smem(((c + 1) & 1) * G1_STAGE);
        __syncthreads();
    }

    // ---- epilogue: dinv scale + fp16 store ----
#pragma unroll
    for (int mi = 0; mi < 4; mi++) {
        int r0 = row0 + warp_m * 64 + mi * 16 + (lane >> 2);
        int r1 = r0 + 8;
        float d0 = (r0 < M) ? g_dinv[r0] : 0.f;
        float d1 = (r1 < M) ? g_dinv[r1] : 0.f;
#pragma unroll
        for (int ni = 0; ni < 4; ni++) {
            int cc = col0 + warp_n * 32 + ni * 8 + (lane & 3) * 2;
            if (r0 < M)
                *(__half2*)&g_y1h[(size_t)r0 * HID + cc] =
                    __floats2half2_rn(d0 * acc[mi][ni][0], d0 * acc[mi][ni][1]);
            if (r1 < M)
                *(__half2*)&g_y1h[(size_t)r1 * HID + cc] =
                    __floats2half2_rn(d1 * acc[mi][ni][2], d1 * acc[mi][ni][3]);
        }
    }
}

// ---------------- Aggregation 1: h = relu(dinv*(sum y1[src] + y1[c]) + b1) ----------------
// one warp per node; lane owns features [8*lane, 8*lane+8) -> one 16B load/edge.
__global__ void k_agg1(const float* __restrict__ b1, int M) {
    int gid  = blockIdx.x * blockDim.x + threadIdx.x;
    int c    = gid >> 5;
    int lane = gid & 31;
    if (c >= M) return;

    const uint4* Y = (const uint4*)g_y1h;    // 32 uint4 per 256-half row
    float a[8];
#pragma unroll
    for (int j = 0; j < 8; j++) a[j] = 0.f;

    int s0 = g_off[c], s1 = g_off[c + 1];
    for (int i = s0; i < s1; i++) {
        int s = g_esrc[i];
        uint4 v = __ldg(Y + (size_t)s * 32 + lane);
        const __half2* h2 = (const __half2*)&v;
#pragma unroll
        for (int j = 0; j < 4; j++) {
            float2 f = __half22float2(h2[j]);
            a[2 * j]     += f.x;
            a[2 * j + 1] += f.y;
        }
    }
    {   // self loop
        uint4 v = __ldg(Y + (size_t)c * 32 + lane);
        const __half2* h2 = (const __half2*)&v;
#pragma unroll
        for (int j = 0; j < 4; j++) {
            float2 f = __half22float2(h2[j]);
            a[2 * j]     += f.x;
            a[2 * j + 1] += f.y;
        }
    }
    float d = g_dinv[c];
    float4 bb0 = *(const float4*)(b1 + lane * 8);
    float4 bb1 = *(const float4*)(b1 + lane * 8 + 4);
    float4 o0, o1;
    o0.x = fmaxf(d * a[0] + bb0.x, 0.f);
    o0.y = fmaxf(d * a[1] + bb0.y, 0.f);
    o0.z = fmaxf(d * a[2] + bb0.z, 0.f);
    o0.w = fmaxf(d * a[3] + bb0.w, 0.f);
    o1.x = fmaxf(d * a[4] + bb1.x, 0.f);
    o1.y = fmaxf(d * a[5] + bb1.y, 0.f);
    o1.z = fmaxf(d * a[6] + bb1.z, 0.f);
    o1.w = fmaxf(d * a[7] + bb1.w, 0.f);
    float* H = &g_h[(size_t)c * HID + lane * 8];
    *(float4*)(H)     = o0;
    *(float4*)(H + 4) = o1;
}

// ---------------- GEMM2: y2 = dinv .* (h @ W2)   [M,256]x[256,40], fp16 out ----------------
__global__ __launch_bounds__(256) void k_sgemm2(const float* __restrict__ W2, int M) {
    __shared__ __align__(16) float hs[16][260];
    __shared__ __align__(16) float ws[16 * NC];
    int tid = threadIdx.x;
    int R0  = blockIdx.x * 256;
    int kv  = tid & 3;
    int rld = tid >> 2;
    int cg  = tid & 3;
    int rq  = tid >> 2;

    float acc[4][10];
#pragma unroll
    for (int i = 0; i < 4; i++)
#pragma unroll
        for (int j = 0; j < 10; j++) acc[i][j] = 0.f;

    for (int k0 = 0; k0 < HID; k0 += 16) {
#pragma unroll
        for (int p = 0; p < 4; p++) {
            int rr = rld + p * 64;
            int gr = R0 + rr;
            float4 v = (gr < M)
                ? *(const float4*)&g_h[(size_t)gr * HID + k0 + kv * 4]
                : make_float4(0.f, 0.f, 0.f, 0.f);
            hs[kv * 4 + 0][rr] = v.x;
            hs[kv * 4 + 1][rr] = v.y;
            hs[kv * 4 + 2][rr] = v.z;
            hs[kv * 4 + 3][rr] = v.w;
        }
        if (tid < 160) {
            const float* wp = W2 + (size_t)k0 * NC + tid * 4;
            ws[tid * 4 + 0] = wp[0];
            ws[tid * 4 + 1] = wp[1];
            ws[tid * 4 + 2] = wp[2];
            ws[tid * 4 + 3] = wp[3];
        }
        __syncthreads();

#pragma unroll
        for (int kk = 0; kk < 16; kk++) {
            float h0 = hs[kk][rq * 4 + 0];
            float h1 = hs[kk][rq * 4 + 1];
            float h2 = hs[kk][rq * 4 + 2];
            float h3 = hs[kk][rq * 4 + 3];
#pragma unroll
            for (int j = 0; j < 10; j++) {
                float w = ws[kk * NC + cg * 10 + j];
                acc[0][j] += h0 * w;
                acc[1][j] += h1 * w;
                acc[2][j] += h2 * w;
                acc[3][j] += h3 * w;
            }
        }
        __syncthreads();
    }

#pragma unroll
    for (int i = 0; i < 4; i++) {
        int r = R0 + rq * 4 + i;
        if (r < M) {
            float d = g_dinv[r];
            __half* yp = &g_y2h[(size_t)r * NC + cg * 10];
#pragma unroll
            for (int j = 0; j < 10; j++) yp[j] = __float2half_rn(d * acc[i][j]);
        }
    }
}

// ---------------- Aggregation 2 + bias + log_softmax ----------------
// one warp per node; lane l<20 owns cols {2l, 2l+1} via one half2 load/edge.
__global__ void k_agg2_softmax(const float* __restrict__ b2,
                               float* __restrict__ out, int M) {
    int gid  = blockIdx.x * blockDim.x + threadIdx.x;
    int c    = gid >> 5;
    int l    = gid & 31;
    if (c >= M) return;

    bool act = (l < 20);
    float ax = 0.f, ay = 0.f;
    int s0 = g_off[c], s1 = g_off[c + 1];
    for (int i = s0; i < s1; i++) {
        int s = g_esrc[i];
        if (act) {
            float2 f = __half22float2(
                __ldg((const __half2*)(g_y2h + (size_t)s * NC) + l));
            ax += f.x; ay += f.y;
        }
    }
    if (act) {
        float2 f = __half22float2(
            __ldg((const __half2*)(g_y2h + (size_t)c * NC) + l));
        ax += f.x; ay += f.y;
    }
    float d  = g_dinv[c];
    float v0 = act ? (d * ax + __ldg(b2 + 2 * l))     : -3.4e38f;
    float v1 = act ? (d * ay + __ldg(b2 + 2 * l + 1)) : -3.4e38f;

    float m = fmaxf(v0, v1);
#pragma unroll
    for (int o = 16; o; o >>= 1) m = fmaxf(m, __shfl_xor_sync(0xffffffffu, m, o));
    float e = act ? (expf(v0 - m) + expf(v1 - m)) : 0.f;
#pragma unroll
    for (int o = 16; o; o >>= 1) e += __shfl_xor_sync(0xffffffffu, e, o);
    float lse = m + logf(e);

    if (act) {
        out[(size_t)c * NC + 2 * l]     = v0 - lse;
        out[(size_t)c * NC + 2 * l + 1] = v1 - lse;
    }
}

// ---------------- launch ----------------
extern "C" void kernel_launch(void* const* d_in, const int* in_sizes, int n_in,
                              void* d_out, int out_size) {
    const float* x   = (const float*)d_in[0];
    const void*  ei  = d_in[1];               // edge_index: int32 OR int64 (detected)
    const float* W1  = (const float*)d_in[2];
    const float* b1  = (const float*)d_in[3];
    const float* W2  = (const float*)d_in[4];
    const float* b2  = (const float*)d_in[5];
    float*       out = (float*)d_out;

    int M = in_sizes[0] / FIN;   // 100000
    int E = in_sizes[1] / 2;     // 3200000

    int tb = 256;
    int gM = (M + tb - 1) / tb;
    int gE = (E + tb - 1) / tb;

    // dtype detection + degree + dinv + W1 prep
    k_detect<<<1, 32>>>(ei, M);
    k_zero_deg<<<gM, tb>>>(M);
    k_hist<<<gE, tb>>>(ei, E);
    k_dinv<<<gM, tb>>>(M);
    k_wprep<<<(HID * FIN + 255) / 256, 256>>>(W1);

    // CSR: scan + fill
    int NB = (M + 1023) / 1024;          // 98
    k_scan1<<<NB, 256>>>(M);
    k_scan2<<<1, 128>>>(NB);
    k_scan3<<<gM, tb>>>(M, E);
    k_fill<<<gE, tb>>>(ei, E);

    // layer 1: tensor-core GEMM (mma.sync, double-buffered) + CSR gather
    cudaFuncSetAttribute(k_mma_gemm1, cudaFuncAttributeMaxDynamicSharedMemorySize,
                         G1_TOT);
    dim3 g1((M + 127) / 128, 2);
    k_mma_gemm1<<<g1, 256, G1_TOT>>>(x, M);
    int gW = ((M * 32) + tb - 1) / tb;   // one warp per node
    k_agg1<<<gW, tb>>>(b1, M);

    // layer 2 + softmax
    k_sgemm2<<<(M + 255) / 256, 256>>>(W2, M);
    k_agg2_softmax<<<gW, tb>>>(b2, out, M);
}

// round 11
// speedup vs baseline: 2.1359x; 1.0308x over previous
#include <cuda_runtime.h>
#include <cuda_fp16.h>
#include <cuda_bf16.h>
#include <math.h>
#include <stdint.h>

#define NMAX 100000
#define EMAX 3200000
#define FIN  512
#define HID  256
#define NC   40

// ---------------- device scratch (static: no allocation) ----------------
__device__ int   g_is64;                  // edge_index dtype flag (1 = int64)
__device__ int   g_deg[NMAX];
__device__ float g_dinv[NMAX];
__device__ int   g_off[NMAX + 1];
__device__ int   g_cur[NMAX];
__device__ int   g_bsum[128];
__device__ int   g_bbase[128];
__device__ int   g_esrc[EMAX];
__device__ __align__(16) __nv_bfloat16 g_w1hi[HID * FIN];  // W1^T [256][512] bf16 hi
__device__ __align__(16) __nv_bfloat16 g_w1lo[HID * FIN];  // W1^T [256][512] bf16 lo
__device__ __align__(16) __half g_y1h[(size_t)NMAX * HID]; // dinv-scaled x@W1 (fp16 msgs)
__device__ __align__(16) __half g_hh [(size_t)NMAX * HID]; // layer-1 output (relu, fp16)
__device__ __align__(16) __half g_y2h[(size_t)NMAX * NC];  // dinv-scaled h@W2 (fp16 msgs)

// ---------------- helpers ----------------
__device__ __forceinline__ uint32_t smem_to_u32(const void* p) {
    uint32_t a;
    asm("{ .reg .u64 t; cvta.to.shared.u64 t, %1; cvt.u32.u64 %0, t; }"
        : "=r"(a) : "l"(p));
    return a;
}
__device__ __forceinline__ uint32_t sw128(uint32_t off) {
    return off ^ ((off >> 3) & 0x70);
}
__device__ __forceinline__ void ldm_x4(uint32_t& r0, uint32_t& r1,
                                       uint32_t& r2, uint32_t& r3, uint32_t a) {
    asm volatile("ldmatrix.sync.aligned.m8n8.x4.shared.b16 {%0,%1,%2,%3}, [%4];"
                 : "=r"(r0), "=r"(r1), "=r"(r2), "=r"(r3) : "r"(a));
}
__device__ __forceinline__ void ldm_x2(uint32_t& r0, uint32_t& r1, uint32_t a) {
    asm volatile("ldmatrix.sync.aligned.m8n8.x2.shared.b16 {%0,%1}, [%2];"
                 : "=r"(r0), "=r"(r1) : "r"(a));
}
__device__ __forceinline__ void mma_bf16(float* c, const uint32_t* a,
                                         const uint32_t* b) {
    asm volatile(
        "mma.sync.aligned.m16n8k16.row.col.f32.bf16.bf16.f32 "
        "{%0,%1,%2,%3}, {%4,%5,%6,%7}, {%8,%9}, {%0,%1,%2,%3};"
        : "+f"(c[0]), "+f"(c[1]), "+f"(c[2]), "+f"(c[3])
        : "r"(a[0]), "r"(a[1]), "r"(a[2]), "r"(a[3]), "r"(b[0]), "r"(b[1]));
}

// ---------------- edge index access (dtype-robust) ----------------
__device__ __forceinline__ int edge_at(const void* ei, int i) {
    if (g_is64) return (int)((const long long*)ei)[i];
    return ((const int*)ei)[i];
}

// ---------------- setup: zero degree + dtype detect (fused) ----------------
__global__ void k_zero_detect(const void* ei, int n) {
    int i = blockIdx.x * blockDim.x + threadIdx.x;
    if (i < n) g_deg[i] = 0;
    if (i == 0) {
        const int* w = (const int*)ei;
        int is64 = 1;
        for (int k = 0; k < 64; k++) {
            int lo = w[2 * k], hi = w[2 * k + 1];
            if (hi != 0 || lo < 0 || lo >= n) { is64 = 0; break; }
        }
        g_is64 = is64;
    }
}

__global__ void k_hist(const void* __restrict__ ei, int E) {
    int e = blockIdx.x * blockDim.x + threadIdx.x;
    if (e < E) atomicAdd(&g_deg[edge_at(ei, E + e)], 1);
}

// W1 [512][256] fp32 -> g_w1hi/g_w1lo [256][512] bf16 (K-major, transposed)
__global__ void k_wprep(const float* __restrict__ W1) {
    int idx = blockIdx.x * blockDim.x + threadIdx.x;   // 0 .. 256*512-1
    if (idx < HID * FIN) {
        int n = idx >> 9, k = idx & 511;
        float w = W1[(size_t)k * HID + n];
        __nv_bfloat16 hi = __float2bfloat16(w);
        __nv_bfloat16 lo = __float2bfloat16(w - __bfloat162float(hi));
        g_w1hi[idx] = hi;
        g_w1lo[idx] = lo;
    }
}

// ---------------- exclusive scan of g_deg -> g_off (+dinv fused) ----------------
__global__ void k_scan1(int n) {
    __shared__ int sdata[256];
    int b = blockIdx.x, t = threadIdx.x;
    int base = b * 1024 + t * 4;
    int v0 = (base + 0 < n) ? g_deg[base + 0] : 0;
    int v1 = (base + 1 < n) ? g_deg[base + 1] : 0;
    int v2 = (base + 2 < n) ? g_deg[base + 2] : 0;
    int v3 = (base + 3 < n) ? g_deg[base + 3] : 0;
    // fused dinv
    if (base + 0 < n) g_dinv[base + 0] = rsqrtf((float)(v0 + 1));
    if (base + 1 < n) g_dinv[base + 1] = rsqrtf((float)(v1 + 1));
    if (base + 2 < n) g_dinv[base + 2] = rsqrtf((float)(v2 + 1));
    if (base + 3 < n) g_dinv[base + 3] = rsqrtf((float)(v3 + 1));
    int tsum = v0 + v1 + v2 + v3;
    sdata[t] = tsum;
    __syncthreads();
    for (int off = 1; off < 256; off <<= 1) {
        int x = 0;
        if (t >= off) x = sdata[t - off];
        __syncthreads();
        sdata[t] += x;
        __syncthreads();
    }
    int run = sdata[t] - tsum;
    if (base + 0 < n) { g_off[base + 0] = run; run += v0; }
    if (base + 1 < n) { g_off[base + 1] = run; run += v1; }
    if (base + 2 < n) { g_off[base + 2] = run; run += v2; }
    if (base + 3 < n) { g_off[base + 3] = run; }
    if (t == 255) g_bsum[b] = sdata[255];
}

__global__ void k_scan2(int nb) {
    __shared__ int s[128];
    int t = threadIdx.x;
    int v = (t < nb) ? g_bsum[t] : 0;
    s[t] = v;
    __syncthreads();
    for (int off = 1; off < 128; off <<= 1) {
        int x = 0;
        if (t >= off) x = s[t - off];
        __syncthreads();
        s[t] += x;
        __syncthreads();
    }
    g_bbase[t] = s[t] - v;
}

__global__ void k_scan3(int n, int E) {
    int i = blockIdx.x * blockDim.x + threadIdx.x;
    if (i < n) {
        int o = g_off[i] + g_bbase[i >> 10];
        g_off[i] = o;
        g_cur[i] = o;
    }
    if (i == 0) g_off[n] = E;
}

__global__ void k_fill(const void* __restrict__ ei, int E) {
    int e = blockIdx.x * blockDim.x + threadIdx.x;
    if (e < E) {
        int r = edge_at(ei, e);          // source
        int c = edge_at(ei, E + e);      // target
        int pos = atomicAdd(&g_cur[c], 1);
        g_esrc[pos] = r;
    }
}

// ---------------- GEMM1 (mma.sync bf16 3-term, double-buffered) ----------------
// CTA tile 128x128, 8 warps (2x4), warp tile 64x32, BK=64 bf16.
// grid = (2 colblocks, rowblocks): x-fastest launch order puts the two CTAs
// sharing an A row-chunk back-to-back -> second one L2-hits on x.
#define G1_AHI 0
#define G1_ALO 16384
#define G1_BHI 32768
#define G1_BLO 49152
#define G1_STAGE 65536
#define G1_TOT (2 * G1_STAGE)

__global__ __launch_bounds__(256, 1) void k_mma_gemm1(const float* __restrict__ A, int M) {
    extern __shared__ char smem[];
    uint32_t sb = smem_to_u32(smem);
    int tid  = threadIdx.x;
    int wid  = tid >> 5;
    int lane = tid & 31;
    int row0 = blockIdx.y * 128;
    int col0 = blockIdx.x * 128;
    int warp_m = wid & 1;          // 0/1 -> 64 rows each
    int warp_n = wid >> 1;         // 0..3 -> 32 cols each

    // ldmatrix per-lane address components
    int a_sel   = lane >> 3;                     // 0..3
    int a_row16 = (lane & 7) + ((a_sel & 1) << 3);
    int a_seg   = a_sel >> 1;                    // 0/1 (k half)
    int b_sel   = (lane >> 3) & 1;               // 0/1 (k half)
    int b_row   = lane & 7;

    float acc[4][4][4];
#pragma unroll
    for (int mi = 0; mi < 4; mi++)
#pragma unroll
        for (int ni = 0; ni < 4; ni++)
#pragma unroll
            for (int q = 0; q < 4; q++) acc[mi][ni][q] = 0.f;

    const char* w1hi = (const char*)g_w1hi;
    const char* w1lo = (const char*)g_w1lo;

    // ---- prefetch registers ----
    float4 av[8];
    uint4  bhv[4], blv[4];

    auto load_regs = [&](int k0) {
#pragma unroll
        for (int i = 0; i < 8; i++) {
            int li = tid + i * 256;
            int r = li >> 4, c4 = li & 15;
            int gr = row0 + r;
            av[i] = (gr < M)
                ? *(const float4*)(A + (size_t)gr * FIN + k0 + c4 * 4)
                : make_float4(0.f, 0.f, 0.f, 0.f);
        }
#pragma unroll
        for (int i = 0; i < 4; i++) {
            int li = tid + i * 256;                // 0..1023
            int r = li >> 3, seg = li & 7;
            size_t gsrc = (size_t)(col0 + r) * (FIN * 2) + (size_t)k0 * 2 + seg * 16;
            bhv[i] = *(const uint4*)(w1hi + gsrc);
            blv[i] = *(const uint4*)(w1lo + gsrc);
        }
    };

    auto store_smem = [&](int so) {
#pragma unroll
        for (int i = 0; i < 8; i++) {
            int li = tid + i * 256;
            int r = li >> 4, c4 = li & 15;
            float4 v = av[i];
            __nv_bfloat162 h01 = make_bfloat162(__float2bfloat16(v.x), __float2bfloat16(v.y));
            __nv_bfloat162 h23 = make_bfloat162(__float2bfloat16(v.z), __float2bfloat16(v.w));
            __nv_bfloat162 l01 = make_bfloat162(
                __float2bfloat16(v.x - __bfloat162float(h01.x)),
                __float2bfloat16(v.y - __bfloat162float(h01.y)));
            __nv_bfloat162 l23 = make_bfloat162(
                __float2bfloat16(v.z - __bfloat162float(h23.x)),
                __float2bfloat16(v.w - __bfloat162float(h23.y)));
            uint32_t off = sw128((uint32_t)(r * 128 + c4 * 8));
            *(__nv_bfloat162*)(smem + so + G1_AHI + off)     = h01;
            *(__nv_bfloat162*)(smem + so + G1_AHI + off + 4) = h23;
            *(__nv_bfloat162*)(smem + so + G1_ALO + off)     = l01;
            *(__nv_bfloat162*)(smem + so + G1_ALO + off + 4) = l23;
        }
#pragma unroll
        for (int i = 0; i < 4; i++) {
            int li = tid + i * 256;
            int r = li >> 3, seg = li & 7;
            uint32_t off = sw128((uint32_t)(r * 128 + seg * 16));
            *(uint4*)(smem + so + G1_BHI + off) = bhv[i];
            *(uint4*)(smem + so + G1_BLO + off) = blv[i];
        }
    };

    load_regs(0);
    store_smem(0);
    __syncthreads();

    for (int c = 0; c < FIN / 64; c++) {          // 8 chunks of K=64
        int cur = (c & 1) * G1_STAGE;
        if (c < 7) load_regs((c + 1) * 64);        // global prefetch (overlaps mma)

        // ---- compute: 4 k16 steps from stage cur ----
#pragma unroll
        for (int ks = 0; ks < 4; ks++) {
            uint32_t ahi[4][4], alo[4][4], bhi[4][2], blo[4][2];
#pragma unroll
            for (int mi = 0; mi < 4; mi++) {
                int row = warp_m * 64 + mi * 16 + a_row16;
                uint32_t off = sw128((uint32_t)(row * 128 + (ks * 2 + a_seg) * 16));
                ldm_x4(ahi[mi][0], ahi[mi][1], ahi[mi][2], ahi[mi][3],
                       sb + cur + G1_AHI + off);
                ldm_x4(alo[mi][0], alo[mi][1], alo[mi][2], alo[mi][3],
                       sb + cur + G1_ALO + off);
            }
#pragma unroll
            for (int ni = 0; ni < 4; ni++) {
                int rn = warp_n * 32 + ni * 8 + b_row;
                uint32_t off = sw128((uint32_t)(rn * 128 + (ks * 2 + b_sel) * 16));
                ldm_x2(bhi[ni][0], bhi[ni][1], sb + cur + G1_BHI + off);
                ldm_x2(blo[ni][0], blo[ni][1], sb + cur + G1_BLO + off);
            }
#pragma unroll
            for (int mi = 0; mi < 4; mi++)
#pragma unroll
                for (int ni = 0; ni < 4; ni++) {
                    mma_bf16(acc[mi][ni], ahi[mi], bhi[ni]);
                    mma_bf16(acc[mi][ni], ahi[mi], blo[ni]);
                    mma_bf16(acc[mi][ni], alo[mi], bhi[ni]);
                }
        }

        if (c < 7) store_smem(((c + 1) & 1) * G1_STAGE);
        __syncthreads();
    }

    // ---- epilogue: dinv scale + fp16 store ----
#pragma unroll
    for (int mi = 0; mi < 4; mi++) {
        int r0 = row0 + warp_m * 64 + mi * 16 + (lane >> 2);
        int r1 = r0 + 8;
        float d0 = (r0 < M) ? g_dinv[r0] : 0.f;
        float d1 = (r1 < M) ? g_dinv[r1] : 0.f;
#pragma unroll
        for (int ni = 0; ni < 4; ni++) {
            int cc = col0 + warp_n * 32 + ni * 8 + (lane & 3) * 2;
            if (r0 < M)
                *(__half2*)&g_y1h[(size_t)r0 * HID + cc] =
                    __floats2half2_rn(d0 * acc[mi][ni][0], d0 * acc[mi][ni][1]);
            if (r1 < M)
                *(__half2*)&g_y1h[(size_t)r1 * HID + cc] =
                    __floats2half2_rn(d1 * acc[mi][ni][2], d1 * acc[mi][ni][3]);
        }
    }
}

// ---------------- Aggregation 1: h = relu(dinv*(sum y1[src] + y1[c]) + b1) ----------------
// one warp per node; lane owns features [8*lane, 8*lane+8) -> one 16B load/edge.
__global__ void k_agg1(const float* __restrict__ b1, int M) {
    int gid  = blockIdx.x * blockDim.x + threadIdx.x;
    int c    = gid >> 5;
    int lane = gid & 31;
    if (c >= M) return;

    const uint4* Y = (const uint4*)g_y1h;    // 32 uint4 per 256-half row
    float a[8];
#pragma unroll
    for (int j = 0; j < 8; j++) a[j] = 0.f;

    int s0 = g_off[c], s1 = g_off[c + 1];
    for (int i = s0; i < s1; i++) {
        int s = g_esrc[i];
        uint4 v = __ldg(Y + (size_t)s * 32 + lane);
        const __half2* h2 = (const __half2*)&v;
#pragma unroll
        for (int j = 0; j < 4; j++) {
            float2 f = __half22float2(h2[j]);
            a[2 * j]     += f.x;
            a[2 * j + 1] += f.y;
        }
    }
    {   // self loop
        uint4 v = __ldg(Y + (size_t)c * 32 + lane);
        const __half2* h2 = (const __half2*)&v;
#pragma unroll
        for (int j = 0; j < 4; j++) {
            float2 f = __half22float2(h2[j]);
            a[2 * j]     += f.x;
            a[2 * j + 1] += f.y;
        }
    }
    float d = g_dinv[c];
    float4 bb0 = *(const float4*)(b1 + lane * 8);
    float4 bb1 = *(const float4*)(b1 + lane * 8 + 4);
    __half2 o[4];
    o[0] = __floats2half2_rn(fmaxf(d * a[0] + bb0.x, 0.f), fmaxf(d * a[1] + bb0.y, 0.f));
    o[1] = __floats2half2_rn(fmaxf(d * a[2] + bb0.z, 0.f), fmaxf(d * a[3] + bb0.w, 0.f));
    o[2] = __floats2half2_rn(fmaxf(d * a[4] + bb1.x, 0.f), fmaxf(d * a[5] + bb1.y, 0.f));
    o[3] = __floats2half2_rn(fmaxf(d * a[6] + bb1.z, 0.f), fmaxf(d * a[7] + bb1.w, 0.f));
    *(uint4*)&g_hh[(size_t)c * HID + lane * 8] = *(uint4*)o;
}

// ---------------- GEMM2: y2 = dinv .* (h @ W2)   [M,256]x[256,40], fp16 in/out ----------------
__global__ __launch_bounds__(256) void k_sgemm2(const float* __restrict__ W2, int M) {
    __shared__ __align__(16) float hs[16][260];
    __shared__ __align__(16) float ws[16 * NC];
    int tid = threadIdx.x;
    int R0  = blockIdx.x * 256;
    int kv  = tid & 3;
    int rld = tid >> 2;
    int cg  = tid & 3;
    int rq  = tid >> 2;

    float acc[4][10];
#pragma unroll
    for (int i = 0; i < 4; i++)
#pragma unroll
        for (int j = 0; j < 10; j++) acc[i][j] = 0.f;

    for (int k0 = 0; k0 < HID; k0 += 16) {
#pragma unroll
        for (int p = 0; p < 4; p++) {
            int rr = rld + p * 64;
            int gr = R0 + rr;
            float2 f0 = make_float2(0.f, 0.f), f1 = f0;
            if (gr < M) {
                uint2 raw = *(const uint2*)&g_hh[(size_t)gr * HID + k0 + kv * 4];
                const __half2* h2 = (const __half2*)&raw;
                f0 = __half22float2(h2[0]);
                f1 = __half22float2(h2[1]);
            }
            hs[kv * 4 + 0][rr] = f0.x;
            hs[kv * 4 + 1][rr] = f0.y;
            hs[kv * 4 + 2][rr] = f1.x;
            hs[kv * 4 + 3][rr] = f1.y;
        }
        if (tid < 160) {
            const float* wp = W2 + (size_t)k0 * NC + tid * 4;
            ws[tid * 4 + 0] = wp[0];
            ws[tid * 4 + 1] = wp[1];
            ws[tid * 4 + 2] = wp[2];
            ws[tid * 4 + 3] = wp[3];
        }
        __syncthreads();

#pragma unroll
        for (int kk = 0; kk < 16; kk++) {
            float h0 = hs[kk][rq * 4 + 0];
            float h1 = hs[kk][rq * 4 + 1];
            float h2 = hs[kk][rq * 4 + 2];
            float h3 = hs[kk][rq * 4 + 3];
#pragma unroll
            for (int j = 0; j < 10; j++) {
                float w = ws[kk * NC + cg * 10 + j];
                acc[0][j] += h0 * w;
                acc[1][j] += h1 * w;
                acc[2][j] += h2 * w;
                acc[3][j] += h3 * w;
            }
        }
        __syncthreads();
    }

#pragma unroll
    for (int i = 0; i < 4; i++) {
        int r = R0 + rq * 4 + i;
        if (r < M) {
            float d = g_dinv[r];
            __half* yp = &g_y2h[(size_t)r * NC + cg * 10];
#pragma unroll
            for (int j = 0; j < 10; j++) yp[j] = __float2half_rn(d * acc[i][j]);
        }
    }
}

// ---------------- Aggregation 2 + bias + log_softmax ----------------
// one warp per node; lane l<20 owns cols {2l, 2l+1} via one half2 load/edge.
__global__ void k_agg2_softmax(const float* __restrict__ b2,
                               float* __restrict__ out, int M) {
    int gid  = blockIdx.x * blockDim.x + threadIdx.x;
    int c    = gid >> 5;
    int l    = gid & 31;
    if (c >= M) return;

    bool act = (l < 20);
    float ax = 0.f, ay = 0.f;
    int s0 = g_off[c], s1 = g_off[c + 1];
    for (int i = s0; i < s1; i++) {
        int s = g_esrc[i];
        if (act) {
            float2 f = __half22float2(
                __ldg((const __half2*)(g_y2h + (size_t)s * NC) + l));
            ax += f.x; ay += f.y;
        }
    }
    if (act) {
        float2 f = __half22float2(
            __ldg((const __half2*)(g_y2h + (size_t)c * NC) + l));
        ax += f.x; ay += f.y;
    }
    float d  = g_dinv[c];
    float v0 = act ? (d * ax + __ldg(b2 + 2 * l))     : -3.4e38f;
    float v1 = act ? (d * ay + __ldg(b2 + 2 * l + 1)) : -3.4e38f;

    float m = fmaxf(v0, v1);
#pragma unroll
    for (int o = 16; o; o >>= 1) m = fmaxf(m, __shfl_xor_sync(0xffffffffu, m, o));
    float e = act ? (expf(v0 - m) + expf(v1 - m)) : 0.f;
#pragma unroll
    for (int o = 16; o; o >>= 1) e += __shfl_xor_sync(0xffffffffu, e, o);
    float lse = m + logf(e);

    if (act) {
        out[(size_t)c * NC + 2 * l]     = v0 - lse;
        out[(size_t)c * NC + 2 * l + 1] = v1 - lse;
    }
}

// ---------------- launch ----------------
extern "C" void kernel_launch(void* const* d_in, const int* in_sizes, int n_in,
                              void* d_out, int out_size) {
    const float* x   = (const float*)d_in[0];
    const void*  ei  = d_in[1];               // edge_index: int32 OR int64 (detected)
    const float* W1  = (const float*)d_in[2];
    const float* b1  = (const float*)d_in[3];
    const float* W2  = (const float*)d_in[4];
    const float* b2  = (const float*)d_in[5];
    float*       out = (float*)d_out;

    int M = in_sizes[0] / FIN;   // 100000
    int E = in_sizes[1] / 2;     // 3200000

    int tb = 256;
    int gM = (M + tb - 1) / tb;
    int gE = (E + tb - 1) / tb;

    // setup: zero+detect, degree histogram, W1 prep
    k_zero_detect<<<gM, tb>>>(ei, M);
    k_hist<<<gE, tb>>>(ei, E);
    k_wprep<<<(HID * FIN + 255) / 256, 256>>>(W1);

    // CSR: scan (+dinv) + fill
    int NB = (M + 1023) / 1024;          // 98
    k_scan1<<<NB, 256>>>(M);
    k_scan2<<<1, 128>>>(NB);
    k_scan3<<<gM, tb>>>(M, E);
    k_fill<<<gE, tb>>>(ei, E);

    // layer 1: tensor-core GEMM (mma.sync, double-buffered) + CSR gather
    cudaFuncSetAttribute(k_mma_gemm1, cudaFuncAttributeMaxDynamicSharedMemorySize,
                         G1_TOT);
    dim3 g1(2, (M + 127) / 128);         // x = colblock (adjacent -> A reuse in L2)
    k_mma_gemm1<<<g1, 256, G1_TOT>>>(x, M);
    int gW = ((M * 32) + tb - 1) / tb;   // one warp per node
    k_agg1<<<gW, tb>>>(b1, M);

    // layer 2 + softmax
    k_sgemm2<<<(M + 255) / 256, 256>>>(W2, M);
    k_agg2_softmax<<<gW, tb>>>(b2, out, M);
}